// round 17
// baseline (speedup 1.0000x reference)
#include <cuda_runtime.h>

#define MAXD 2048
#define NTMAX 64
#define ETA 0.005f

// Disjoint partials; every slot written exactly once per launch.
__device__ float g_partM[NTMAX][MAXD];   // 512 KB
__device__ float g_partR[NTMAX][MAXD];   // 512 KB
__device__ float g_m[MAXD];              // m[j]  (pre-scaled by 1/D)
__device__ float g_rm[MAXD];             // rowmean[b] * ETA / D
__device__ unsigned int g_ctr[NTMAX];    // per-tile arrival weights (self-resetting)

// ---------------------------------------------------------------------------
// Kernel 1: symmetric strip-pair reduction (r16 core, measured fast) PLUS
// event-driven per-tile final reduce (removes the separate reduce node).
// Block (I, JB=2bx): A-strip = x[I, JB..JB+1] (32x64), B-strip (64x32),
// cp.async loads. 8 warps: combo c = (pair j, pass) x half.
// Tile T's 64 partial slots: pass1 -> p=0..T, pass2 -> p=T+1..63.
// After partial stores: writers fence, tid0 adds weights to g_ctr[T]; the
// block completing T reduces its 64x32 partials into g_m/g_rm (no waiting).
// ---------------------------------------------------------------------------
__global__ void __launch_bounds__(256) hebb_tile_kernel(
    const float* __restrict__ x, int D, float invD)
{
    const int I  = blockIdx.y;
    const int JB = blockIdx.x << 1;
    if (JB + 1 < I) return;            // fully lower-triangle: no-op

    __shared__ float4 As4[32][17];     // word stride 68
    __shared__ float4 Bs4[64][9];      // word stride 36
    __shared__ float2 redHi[4][32];
    __shared__ float2 redT[8][32];
    __shared__ int doT[3];

    const int tid = threadIdx.x;
    const int r   = tid >> 3;          // 0..31
    const int c8  = tid & 7;           // 0..7

    {   // A-strip: 2 cp.async per thread (coalesced 128B per 8-lane group)
        const float* arow = x + (size_t)(I * 32 + r) * D + JB * 32;
        #pragma unroll
        for (int jj = 0; jj < 2; jj++) {
            unsigned d = (unsigned)__cvta_generic_to_shared(&As4[r][jj * 8 + c8]);
            asm volatile("cp.async.cg.shared.global [%0], [%1], 16;"
                         :: "r"(d), "l"(arow + ((jj * 8 + c8) << 2)));
        }
    }
    #pragma unroll
    for (int jj = 0; jj < 2; jj++) {   // B-strip: 2 more
        const int rb = jj * 32 + r;
        unsigned d = (unsigned)__cvta_generic_to_shared(&Bs4[rb][c8]);
        asm volatile("cp.async.cg.shared.global [%0], [%1], 16;"
                     :: "r"(d), "l"(x + (size_t)(JB * 32 + rb) * D + I * 32 + (c8 << 2)));
    }
    asm volatile("cp.async.commit_group;");
    asm volatile("cp.async.wait_group 0;");
    __syncthreads();

    const int w = tid >> 5, l = tid & 31;
    const int c = w & 3, half = w >> 2;      // combo 0..3, half 0..1
    const int j = c >> 1, which = c & 1;
    const int J = JB + j;

    const float* Af = reinterpret_cast<const float*>(As4);
    const float* Bf = reinterpret_cast<const float*>(Bs4);

    float sm = 0.0f, sr = 0.0f;
    if (which == 0) {
        const int acol = (j << 5) + l;
        const float4* brow = Bs4[(j << 5) + l] + (half << 2);  // LDS.128, c-free
        #pragma unroll
        for (int q = 0; q < 4; q++) {
            const float4 b = brow[q];
            const int u = (((half << 2) + q) << 2);
            sm += Af[(u + 0) * 68 + acol] * b.x + Af[(u + 1) * 68 + acol] * b.y
                + Af[(u + 2) * 68 + acol] * b.z + Af[(u + 3) * 68 + acol] * b.w;
            sr += (b.x + b.y) + (b.z + b.w);
        }
    } else {
        const float4* arow4 = As4[l] + (j << 3) + (half << 2);  // LDS.128, c-free
        #pragma unroll
        for (int q = 0; q < 4; q++) {
            const float4 a = arow4[q];
            const int v = (j << 5) + (((half << 2) + q) << 2);
            sm += a.x * Bf[(v + 0) * 36 + l] + a.y * Bf[(v + 1) * 36 + l]
                + a.z * Bf[(v + 2) * 36 + l] + a.w * Bf[(v + 3) * 36 + l];
            sr += (a.x + a.y) + (a.z + a.w);
        }
    }
    if (half) redHi[c][l] = make_float2(sm, sr);
    __syncthreads();
    if (!half) {
        const float2 h = redHi[c][l];
        sm += h.x; sr += h.y;
        if (which == 0) {
            if (J >= I) { g_partM[I][J * 32 + l] = sm; g_partR[I][J * 32 + l] = sr; }
        } else {
            if (J > I)  { g_partM[J][I * 32 + l] = sm; g_partR[J][I * 32 + l] = sr; }
        }
        __threadfence();               // publish this block's partials (writers only)
    }
    __syncthreads();

    // tid0: arrive with per-tile weights; detect completed tiles.
    if (tid == 0) {
        doT[0] = doT[1] = doT[2] = -1;
        int      tiles[3] = { JB, JB + 1, I };
        unsigned wts[3];
        wts[0] = (JB >= I) ? 1u : 0u;                       // pass1 J=JB
        wts[1] = 1u;                                        // pass1 J=JB+1
        wts[2] = (unsigned)((JB > I) + (JB + 1 > I));       // pass2 -> tile I
        if (I == JB)          { wts[0] += wts[2]; wts[2] = 0; }
        else if (I == JB + 1) { wts[1] += wts[2]; wts[2] = 0; }
        int nd = 0;
        #pragma unroll
        for (int k = 0; k < 3; k++) {
            if (wts[k] == 0) continue;
            unsigned old = atomicAdd(&g_ctr[tiles[k]], wts[k]);
            if (old + wts[k] == 64u) doT[nd++] = tiles[k];
        }
        if (nd > 0) __threadfence();   // acquire: all partials for won tiles visible
    }
    __syncthreads();

    // Reduce any tiles this block completed (no block ever waits).
    #pragma unroll
    for (int s = 0; s < 3; s++) {
        const int T = doT[s];
        if (T < 0) continue;
        const int lane = tid & 31, g = tid >> 5;
        float sm2 = 0.0f, sr2 = 0.0f;
        #pragma unroll
        for (int k = 0; k < 8; k++) {
            const int p = (g << 3) + k;
            sm2 += g_partM[p][T * 32 + lane];
            sr2 += g_partR[p][T * 32 + lane];
        }
        redT[g][lane] = make_float2(sm2, sr2);
        __syncthreads();
        if (tid < 32) {
            float m = 0.0f, rr = 0.0f;
            #pragma unroll
            for (int k = 0; k < 8; k++) { m += redT[k][tid].x; rr += redT[k][tid].y; }
            g_m[T * 32 + tid]  = m * invD;
            g_rm[T * 32 + tid] = rr * (invD * ETA);
            if (tid == 0) g_ctr[T] = 0;     // replay-deterministic reset
        }
        __syncthreads();
    }
}

// ---------------------------------------------------------------------------
// Kernel 2 (D==2048): elementwise outputs (UNCHANGED from r16).
// 1024 blocks x 2 rows; 8 front-batched LDG.128 + broadcast rm loads.
//   y[i,j]  = kernel[i,j] * m[j]
//   nk[i,j] = kernel[i,j] + rm[i] * x[i,j]
// ---------------------------------------------------------------------------
template<bool NK>
__global__ void __launch_bounds__(256) hebb_ew_kernel_s(
    const float* __restrict__ x, const float* __restrict__ kmat,
    float* __restrict__ y, float* __restrict__ nk)
{
    const int tid = threadIdx.x;
    const int c0 = tid, c1 = tid + 256;
    const int row = blockIdx.x << 1;
    const size_t b0 = (size_t)row << 9;    // row * 512 float4
    const size_t b1 = b0 + 512;

    const float4* k0 = reinterpret_cast<const float4*>(kmat) + b0;
    const float4* k1 = reinterpret_cast<const float4*>(kmat) + b1;
    const float4* x0 = reinterpret_cast<const float4*>(x) + b0;
    const float4* x1 = reinterpret_cast<const float4*>(x) + b1;
    const float4* m4 = reinterpret_cast<const float4*>(g_m);

    float4 ka0 = k0[c0], kb0 = k0[c1], ka1 = k1[c0], kb1 = k1[c1];
    float4 ma = m4[c0], mb = m4[c1];
    float4 xa0, xb0, xa1, xb1;
    if (NK) { xa0 = x0[c0]; xb0 = x0[c1]; xa1 = x1[c0]; xb1 = x1[c1]; }
    const float rm0 = g_rm[row];
    const float rm1 = g_rm[row + 1];

    float4* y0 = reinterpret_cast<float4*>(y) + b0;
    float4* y1 = reinterpret_cast<float4*>(y) + b1;

    float4 v;
    v.x = ka0.x * ma.x; v.y = ka0.y * ma.y; v.z = ka0.z * ma.z; v.w = ka0.w * ma.w;
    y0[c0] = v;
    v.x = kb0.x * mb.x; v.y = kb0.y * mb.y; v.z = kb0.z * mb.z; v.w = kb0.w * mb.w;
    y0[c1] = v;
    v.x = ka1.x * ma.x; v.y = ka1.y * ma.y; v.z = ka1.z * ma.z; v.w = ka1.w * ma.w;
    y1[c0] = v;
    v.x = kb1.x * mb.x; v.y = kb1.y * mb.y; v.z = kb1.z * mb.z; v.w = kb1.w * mb.w;
    y1[c1] = v;

    if (NK) {
        float4* n0 = reinterpret_cast<float4*>(nk) + b0;
        float4* n1 = reinterpret_cast<float4*>(nk) + b1;
        v.x = fmaf(rm0, xa0.x, ka0.x); v.y = fmaf(rm0, xa0.y, ka0.y);
        v.z = fmaf(rm0, xa0.z, ka0.z); v.w = fmaf(rm0, xa0.w, ka0.w);
        n0[c0] = v;
        v.x = fmaf(rm0, xb0.x, kb0.x); v.y = fmaf(rm0, xb0.y, kb0.y);
        v.z = fmaf(rm0, xb0.z, kb0.z); v.w = fmaf(rm0, xb0.w, kb0.w);
        n0[c1] = v;
        v.x = fmaf(rm1, xa1.x, ka1.x); v.y = fmaf(rm1, xa1.y, ka1.y);
        v.z = fmaf(rm1, xa1.z, ka1.z); v.w = fmaf(rm1, xa1.w, ka1.w);
        n1[c0] = v;
        v.x = fmaf(rm1, xb1.x, kb1.x); v.y = fmaf(rm1, xb1.y, kb1.y);
        v.z = fmaf(rm1, xb1.z, kb1.z); v.w = fmaf(rm1, xb1.w, kb1.w);
        n1[c1] = v;
    }
}

// ------------------- generic fallback path (non-2048 D) --------------------
__global__ void __launch_bounds__(256) hebb_reduce_kernel(int NT, float invD)
{
    __shared__ float sM[8][33];
    __shared__ float sR[8][33];
    const int lane = threadIdx.x & 31;
    const int g    = threadIdx.x >> 5;
    const int jj0  = blockIdx.x * 32;
    float sm = 0.0f, sr = 0.0f;
    for (int p = g; p < NT; p += 8) { sm += g_partM[p][jj0 + lane]; sr += g_partR[p][jj0 + lane]; }
    sM[g][lane] = sm; sR[g][lane] = sr;
    __syncthreads();
    if (threadIdx.x < 32) {
        float m = 0.0f, r = 0.0f;
        #pragma unroll
        for (int k = 0; k < 8; k++) { m += sM[k][threadIdx.x]; r += sR[k][threadIdx.x]; }
        g_m[jj0 + threadIdx.x]  = m * invD;
        g_rm[jj0 + threadIdx.x] = r * (invD * ETA);
    }
}

__global__ void __launch_bounds__(256) hebb_ew_kernel_g(
    const float* __restrict__ x, const float* __restrict__ kmat,
    float* __restrict__ y, float* __restrict__ nk, int D4, int n4, int write_nk)
{
    int idx = blockIdx.x * 256 + threadIdx.x;
    if (idx >= n4) return;
    const int col4 = idx % D4;
    const int row  = idx / D4;
    float4 kv = reinterpret_cast<const float4*>(kmat)[idx];
    float4 mv = reinterpret_cast<const float4*>(g_m)[col4];
    float4 yv;
    yv.x = kv.x * mv.x; yv.y = kv.y * mv.y; yv.z = kv.z * mv.z; yv.w = kv.w * mv.w;
    reinterpret_cast<float4*>(y)[idx] = yv;
    if (write_nk) {
        float rm = g_rm[row];
        float4 xv = reinterpret_cast<const float4*>(x)[idx];
        float4 nv;
        nv.x = fmaf(rm, xv.x, kv.x); nv.y = fmaf(rm, xv.y, kv.y);
        nv.z = fmaf(rm, xv.z, kv.z); nv.w = fmaf(rm, xv.w, kv.w);
        reinterpret_cast<float4*>(nk)[idx] = nv;
    }
}

extern "C" void kernel_launch(void* const* d_in, const int* in_sizes, int n_in,
                              void* d_out, int out_size)
{
    if (n_in < 2 || !d_in || !d_out || !in_sizes) return;

    const float* x    = (const float*)d_in[0];
    const float* kmat = (const float*)d_in[1];
    float* out        = (float*)d_out;

    const int n = in_sizes[0];           // D*D
    int D = 1;
    while (D < MAXD && D * D < n) D++;   // D = 2048 here
    if (D * D != n || (D % 64) != 0) return;

    const int NT = D / 32;
    const int write_nk = (out_size >= 2 * n) ? 1 : 0;
    const float invD = 1.0f / (float)D;

    float* y  = out;
    float* nk = out + n;

    dim3 tgrid(NT / 2, NT);              // (32, 64) for D=2048
    hebb_tile_kernel<<<tgrid, 256>>>(x, D, invD);

    if (D == 2048) {
        if (write_nk)
            hebb_ew_kernel_s<true><<<1024, 256>>>(x, kmat, y, nk);
        else
            hebb_ew_kernel_s<false><<<1024, 256>>>(x, kmat, y, nk);
    } else {
        hebb_reduce_kernel<<<D / 32, 256>>>(NT, invD);
        const int n4 = n >> 2;
        hebb_ew_kernel_g<<<(n4 + 255) / 256, 256>>>(x, kmat, y, nk, D >> 2, n4, write_nk);
    }
}